// round 15
// baseline (speedup 1.0000x reference)
#include <cuda_runtime.h>
#include <cuda_fp16.h>
#include <cstdint>

#define DDIM 256
#define NROWS 65536
#define KCODES 1024
#define BM 128
#define BN 128
#define BK 64                 // halves per B stage (128 bytes/row)
#define NCH 8                 // code chunks (1024/128)
#define KS 4                  // k-stages per chunk (256/64)
#define NGS (NCH*KS)          // 32 flat B stages
#define A_BYTES 65536         // resident A: 128 rows x 512 B
#define STG_B 16384           // B stage: 128 rows x 128 B
#define INFV 3.4e38f
#define OUTRPB 16
#define RGRID 256

__device__ __half g_zh[(size_t)NROWS * DDIM];    // 32 MB
__device__ __half g_wh[(size_t)KCODES * DDIM];
__device__ float g_wt[DDIM * KCODES];            // transposed fp32 codebook (refine)
__device__ float g_cnorm[KCODES];
__device__ float g_me[NROWS];                    // per-row certified margin
__device__ float g_zn2[NROWS];                   // exact ||z_row||^2
__device__ float g_dist[NROWS];                  // best (cn - 2*dot) per row
__device__ int   g_wmaxbits;
__device__ int   g_dwmaxbits;
__device__ int   g_idx[NROWS];
__device__ int   g_flaglist[NROWS];
__device__ int   g_flagcount;

__device__ __forceinline__ unsigned h2_bits(__half2 h) {
    unsigned u;
    memcpy(&u, &h, 4);
    return u;
}

// ---------------- init / noop (launch-slot alignment for ncu) ----------------
__global__ void init_kernel() {
    g_flagcount = 0;
    g_wmaxbits = 0;
    g_dwmaxbits = 0;
}
__global__ void noop_kernel() {}

// ---------------- prep: quantize w + cnorm + transpose (fused) ----------------
__global__ void quant_w_kernel(const float* __restrict__ w) {
    int warp = threadIdx.x >> 5, lane = threadIdx.x & 31;
    int row = blockIdx.x * 8 + warp;
    const float4* wr = (const float4*)(w + (size_t)row * DDIM);
    float4 v0 = wr[lane * 2], v1 = wr[lane * 2 + 1];
    float v[8] = {v0.x, v0.y, v0.z, v0.w, v1.x, v1.y, v1.z, v1.w};
    __half h[8];
    float sd2 = 0.f, sw2 = 0.f;
    #pragma unroll
    for (int i = 0; i < 8; i++) {
        h[i] = __float2half_rn(v[i]);
        float d = v[i] - __half2float(h[i]);   // exact
        sd2 += d * d;
        sw2 += v[i] * v[i];
        g_wt[(size_t)(lane * 8 + i) * KCODES + row] = v[i];   // transposed copy
    }
    #pragma unroll
    for (int o = 16; o; o >>= 1) {
        sd2 += __shfl_xor_sync(0xffffffffu, sd2, o);
        sw2 += __shfl_xor_sync(0xffffffffu, sw2, o);
    }
    *(uint4*)(g_wh + (size_t)row * DDIM + lane * 8) = *(uint4*)h;
    if (lane == 0) {
        g_cnorm[row] = sw2;
        float wn  = sqrtf(sw2) * 1.0001f + 1e-8f;
        float dwn = sqrtf(sd2) * 1.0001f + 1e-8f;
        atomicMax(&g_wmaxbits, __float_as_int(wn));
        atomicMax(&g_dwmaxbits, __float_as_int(dwn));
    }
}

// quant_z: single reduction (exact ||z||^2); margin from certified relative bounds
__global__ void quant_z_kernel(const float* __restrict__ z) {
    int warp = threadIdx.x >> 5, lane = threadIdx.x & 31;
    int row = blockIdx.x * 8 + warp;
    const float4* zr = (const float4*)(z + (size_t)row * DDIM);
    float4 v0 = zr[lane * 2], v1 = zr[lane * 2 + 1];
    float sz2 = v0.x*v0.x + v0.y*v0.y + v0.z*v0.z + v0.w*v0.w
              + v1.x*v1.x + v1.y*v1.y + v1.z*v1.z + v1.w*v1.w;
    __half2 h01 = __float22half2_rn(make_float2(v0.x, v0.y));
    __half2 h23 = __float22half2_rn(make_float2(v0.z, v0.w));
    __half2 h45 = __float22half2_rn(make_float2(v1.x, v1.y));
    __half2 h67 = __float22half2_rn(make_float2(v1.z, v1.w));
    #pragma unroll
    for (int o = 16; o; o >>= 1)
        sz2 += __shfl_xor_sync(0xffffffffu, sz2, o);
    uint4 pk;
    pk.x = h2_bits(h01); pk.y = h2_bits(h23);
    pk.z = h2_bits(h45); pk.w = h2_bits(h67);
    *(uint4*)(g_zh + (size_t)row * DDIM + lane * 8) = pk;
    if (lane == 0) {
        g_zn2[row] = sz2;
        float szn = sqrtf(sz2);
        // certified bounds: ||dz|| <= 4.9e-4*||z|| + eps ; ||zh|| <= 1.001*||z||
        float dzn = 4.9e-4f * szn + 1e-5f;
        float zhn = 1.001f * szn;
        float wmax  = __int_as_float(g_wmaxbits);
        float dwmax = __int_as_float(g_dwmaxbits);
        g_me[row] = 4.f * (dzn * wmax + zhn * dwmax) + 0.01f;
    }
}

// ---------------- GEMM helpers ----------------
__device__ __forceinline__ void cp16(unsigned saddr, const void* gaddr) {
    asm volatile("cp.async.cg.shared.global [%0], [%1], 16;\n" :: "r"(saddr), "l"(gaddr) : "memory");
}
__device__ __forceinline__ void cp_commit() { asm volatile("cp.async.commit_group;\n" ::: "memory"); }
template<int P> __device__ __forceinline__ void cp_wait() {
    asm volatile("cp.async.wait_group %0;\n" :: "n"(P) : "memory");
}
__device__ __forceinline__ void ldsm4(unsigned a, unsigned &r0, unsigned &r1, unsigned &r2, unsigned &r3) {
    asm volatile("ldmatrix.sync.aligned.m8n8.x4.shared.b16 {%0,%1,%2,%3}, [%4];"
                 : "=r"(r0), "=r"(r1), "=r"(r2), "=r"(r3) : "r"(a));
}
__device__ __forceinline__ void mma16816(float* c, const unsigned* a, const unsigned* b) {
    asm volatile("mma.sync.aligned.m16n8k16.row.col.f32.f16.f16.f32 "
                 "{%0,%1,%2,%3}, {%4,%5,%6,%7}, {%8,%9}, {%0,%1,%2,%3};"
                 : "+f"(c[0]), "+f"(c[1]), "+f"(c[2]), "+f"(c[3])
                 : "r"(a[0]), "r"(a[1]), "r"(a[2]), "r"(a[3]), "r"(b[0]), "r"(b[1]));
}
__device__ __forceinline__ bool lexless(float v, int i, float w, int j) {
    return v < w || (v == w && i < j);
}
__device__ __forceinline__ void top2_merge(float &v1, int &i1, float &v2, int &i2,
                                           float w1, int j1, float w2, int j2) {
    if (lexless(w1, j1, v1, i1)) {
        float nv2; int ni2;
        if (lexless(v1, i1, w2, j2)) { nv2 = v1; ni2 = i1; } else { nv2 = w2; ni2 = j2; }
        v1 = w1; i1 = j1; v2 = nv2; i2 = ni2;
    } else if (lexless(w1, j1, v2, i2)) {
        v2 = w1; i2 = j1;
    }
}

// B-tile swizzle (128B rows): chunk s (16B) of row r -> s ^ (r&7)
__device__ __forceinline__ unsigned sw_off(int row, int bytecol) {
    unsigned off = (unsigned)(row * 128 + bytecol);
    return off ^ ((unsigned)(row & 7) << 4);
}
// A-resident swizzle (512B rows): 16B chunk c of row r -> c ^ (r&7) (low 3 bits)
__device__ __forceinline__ unsigned sw_offA(int row, int c16) {
    return (unsigned)(row * 512) + ((unsigned)(c16 ^ (row & 7)) << 4);
}

// ---------------- main fp16 GEMM (R12 config: A-resident, B double-buffered) ----------------
__global__ void __launch_bounds__(256, 2)
gemm_kernel(int N, int K)
{
    extern __shared__ __align__(128) char dynsmem[];   // [A 64K | B0 16K | B1 16K]
    __shared__ float  s_cn[KCODES];
    __shared__ float4 s_part[2][BM];

    const int tid  = threadIdx.x;
    const int lane = tid & 31;
    const int warp = tid >> 5;      // 0..7
    const int mw   = warp & 3;      // 4 m-warps
    const int nw   = warp >> 2;     // 2 n-warps
    const int wm0  = mw * 32;
    const int wn0  = nw * 64;
    const int rowBase = blockIdx.x * BM;

    const unsigned sbase = (unsigned)__cvta_generic_to_shared(dynsmem);
    const unsigned bring = sbase + A_BYTES;

    #pragma unroll
    for (int i = tid; i < KCODES; i += 256) s_cn[i] = g_cnorm[i];

    // ---- one-time A load: 128 rows x 512B, swizzled ----
    {
        const __half* zp = g_zh + (size_t)(rowBase + (tid >> 1)) * DDIM + (tid & 1) * 128;
        int r = tid >> 1;
        int c0 = (tid & 1) * 16;
        #pragma unroll
        for (int it = 0; it < 16; it++)
            cp16(sbase + sw_offA(r, c0 + it), zp + it * 8);
        cp_commit();
    }

    const __half* wptr = g_wh + (size_t)(tid >> 3) * DDIM + (tid & 7) * 8;
    const unsigned bsw0 = sw_off(tid >> 3, (tid & 7) * 16);

    auto load_B = [&](int gs) {
        unsigned bs_ = bring + (unsigned)(gs & 1) * STG_B;
        const __half* pb = wptr + (gs >> 2) * (BN * DDIM) + (gs & 3) * BK;
        #pragma unroll
        for (int it = 0; it < 4; it++)
            cp16(bs_ + bsw0 + it * 4096, pb + it * 32 * DDIM);
        cp_commit();
    };

    unsigned aAbase[2], a6[2];
    #pragma unroll
    for (int i = 0; i < 2; i++) {
        int arow = wm0 + i * 16 + (lane & 15);
        aAbase[i] = (unsigned)(arow * 512) + ((unsigned)(((lane >> 4) ^ arow) & 1) << 4);
        a6[i] = (unsigned)(arow & 6) << 4;
    }
    unsigned boff[4];
    #pragma unroll
    for (int p = 0; p < 4; p++)
        boff[p] = sw_off(wn0 + p * 16 + (lane & 7) + ((lane >> 4) << 3),
                         (((lane >> 3) & 1) << 3) * 2);

    float rv1[4], rv2[4];
    int   ri1[4], ri2[4];
    #pragma unroll
    for (int s = 0; s < 4; s++) { rv1[s] = INFV; rv2[s] = INFV; ri1[s] = 0x7fffffff; ri2[s] = 0x7fffffff; }

    load_B(0);

    for (int ch = 0; ch < NCH; ch++) {
        float acc[2][8][4];
        #pragma unroll
        for (int i = 0; i < 2; i++)
            #pragma unroll
            for (int j = 0; j < 8; j++)
                #pragma unroll
                for (int c = 0; c < 4; c++) acc[i][j][c] = 0.f;

        #pragma unroll
        for (int ks = 0; ks < KS; ks++) {
            const int gs = ch * KS + ks;
            cp_wait<0>();
            __syncthreads();
            if (gs + 1 < NGS) load_B(gs + 1);

            const unsigned bbase = bring + (unsigned)(gs & 1) * STG_B;
            #pragma unroll
            for (int kk = 0; kk < BK; kk += 16) {
                const unsigned kkb = (unsigned)kk * 2;
                unsigned a[2][4];
                #pragma unroll
                for (int i = 0; i < 2; i++)
                    ldsm4(sbase + aAbase[i] + (unsigned)(ks * 128) + (kkb ^ a6[i]),
                          a[i][0], a[i][1], a[i][2], a[i][3]);
                unsigned b[8][2];
                #pragma unroll
                for (int p = 0; p < 4; p++)
                    ldsm4(bbase + (boff[p] ^ kkb), b[2*p][0], b[2*p][1], b[2*p+1][0], b[2*p+1][1]);
                #pragma unroll
                for (int i = 0; i < 2; i++)
                    #pragma unroll
                    for (int j = 0; j < 8; j++)
                        mma16816(acc[i][j], a[i], b[j]);
            }
        }

        // ---- per-thread scoring: ascending idx + strict < == lex-min ----
        #pragma unroll
        for (int i = 0; i < 2; i++) {
            #pragma unroll
            for (int h = 0; h < 2; h++) {
                const int s = i * 2 + h;
                float v1 = rv1[s], v2 = rv2[s];
                int   i1 = ri1[s], i2 = ri2[s];
                #pragma unroll
                for (int j = 0; j < 8; j++) {
                    #pragma unroll
                    for (int c = 0; c < 2; c++) {
                        int col = wn0 + j * 8 + (lane & 3) * 2 + c;
                        int idx = ch * BN + col;
                        float val = fmaf(-2.f, acc[i][j][h * 2 + c], s_cn[idx]);
                        if (val < v1) { v2 = v1; i2 = i1; v1 = val; i1 = idx; }
                        else if (val < v2) { v2 = val; i2 = idx; }
                    }
                }
                rv1[s] = v1; rv2[s] = v2; ri1[s] = i1; ri2[s] = i2;
            }
        }
    }

    // ---- final cross-thread merge (once) ----
    #pragma unroll
    for (int s = 0; s < 4; s++) {
        float v1 = rv1[s], v2 = rv2[s];
        int   i1 = ri1[s], i2 = ri2[s];
        #pragma unroll
        for (int off = 1; off < 4; off <<= 1) {
            float ov1 = __shfl_xor_sync(0xffffffffu, v1, off);
            int   oi1 = __shfl_xor_sync(0xffffffffu, i1, off);
            float ov2 = __shfl_xor_sync(0xffffffffu, v2, off);
            int   oi2 = __shfl_xor_sync(0xffffffffu, i2, off);
            top2_merge(v1, i1, v2, i2, ov1, oi1, ov2, oi2);
        }
        if ((lane & 3) == 0) {
            int i = s >> 1, h = s & 1;
            int r = wm0 + i * 16 + (lane >> 2) + h * 8;
            s_part[nw][r] = make_float4(v1, __int_as_float(i1), v2, __int_as_float(i2));
        }
    }
    __syncthreads();
    if (tid < BM) {
        float4 pa = s_part[0][tid];
        float4 pb = s_part[1][tid];
        float v1 = pa.x; int i1 = __float_as_int(pa.y);
        float v2 = pa.z; int i2 = __float_as_int(pa.w);
        top2_merge(v1, i1, v2, i2, pb.x, __float_as_int(pb.y), pb.z, __float_as_int(pb.w));
        int row = rowBase + tid;
        g_idx[row] = i1;
        g_dist[row] = v1;
        if (v2 - v1 <= g_me[row]) {
            int pos = atomicAdd(&g_flagcount, 1);
            g_flaglist[pos] = row;
        }
    }
}

// ---------------- exact refine of flagged rows (wT-based, FMA-bound) ----------------
__global__ void refine_kernel(const float* __restrict__ z, int K) {
    __shared__ __align__(16) float zs[8][260];
    __shared__ int   rowids[8];
    __shared__ float sbv[8][8];
    __shared__ int   sbi[8][8];

    const int tid  = threadIdx.x;
    const int lane = tid & 31;
    const int warp = tid >> 5;
    const int fcount = g_flagcount;

    for (int base = blockIdx.x * 8; base < fcount; base += gridDim.x * 8) {
        int cnt = min(8, fcount - base);
        if (tid < cnt) rowids[tid] = g_flaglist[base + tid];
        __syncthreads();
        for (int e = tid; e < cnt * 256; e += 256)
            zs[e >> 8][e & 255] = z[(size_t)rowids[e >> 8] * DDIM + (e & 255)];
        __syncthreads();

        float bv[8]; int bi[8];
        #pragma unroll
        for (int r = 0; r < 8; r++) { bv[r] = INFV; bi[r] = 0x7fffffff; }

        #pragma unroll 1
        for (int p = 0; p < 4; p++) {
            int k = p * 256 + tid;
            float acc[8];
            #pragma unroll
            for (int r = 0; r < 8; r++) acc[r] = 0.f;
            #pragma unroll 4
            for (int d4 = 0; d4 < 64; d4++) {
                float w0 = g_wt[(size_t)(d4 * 4 + 0) * KCODES + k];
                float w1 = g_wt[(size_t)(d4 * 4 + 1) * KCODES + k];
                float w2 = g_wt[(size_t)(d4 * 4 + 2) * KCODES + k];
                float w3 = g_wt[(size_t)(d4 * 4 + 3) * KCODES + k];
                #pragma unroll
                for (int r = 0; r < 8; r++) {
                    float4 zv = *(const float4*)&zs[r][d4 * 4];
                    acc[r] = fmaf(zv.x, w0, acc[r]);
                    acc[r] = fmaf(zv.y, w1, acc[r]);
                    acc[r] = fmaf(zv.z, w2, acc[r]);
                    acc[r] = fmaf(zv.w, w3, acc[r]);
                }
            }
            float cn = g_cnorm[k];
            #pragma unroll
            for (int r = 0; r < 8; r++) {
                float val = fmaf(-2.f, acc[r], cn);
                if (lexless(val, k, bv[r], bi[r])) { bv[r] = val; bi[r] = k; }
            }
        }

        #pragma unroll
        for (int r = 0; r < 8; r++) {
            float v = bv[r]; int i = bi[r];
            #pragma unroll
            for (int off = 16; off; off >>= 1) {
                float ov = __shfl_xor_sync(0xffffffffu, v, off);
                int   oi = __shfl_xor_sync(0xffffffffu, i, off);
                if (lexless(ov, oi, v, i)) { v = ov; i = oi; }
            }
            if (lane == 0) { sbv[warp][r] = v; sbi[warp][r] = i; }
        }
        __syncthreads();
        if (tid < cnt) {
            float v = sbv[0][tid]; int i = sbi[0][tid];
            #pragma unroll
            for (int wq = 1; wq < 8; wq++)
                if (lexless(sbv[wq][tid], sbi[wq][tid], v, i)) { v = sbv[wq][tid]; i = sbi[wq][tid]; }
            g_idx[rowids[tid]] = i;
            g_dist[rowids[tid]] = v;
        }
        __syncthreads();
    }
}

// ---------------- output assembly (idx + z_q gather; float4 reads) ----------------
__global__ void output_kernel(const float* __restrict__ w, float* __restrict__ out, int N)
{
    __shared__ int s_idx[OUTRPB];
    const int tid = threadIdx.x;
    const int base = blockIdx.x * OUTRPB;

    float* out_zq  = out + 1;
    float* out_idx = out + 1 + (size_t)N * DDIM;

    if (tid < OUTRPB) {
        int ix = g_idx[base + tid];
        s_idx[tid] = ix;
        out_idx[base + tid] = (float)ix;
    }
    __syncthreads();

    #pragma unroll
    for (int i = tid; i < OUTRPB * 64; i += 256) {
        int r = i >> 6, c = i & 63;
        float4 v = *(const float4*)(w + (size_t)s_idx[r] * DDIM + c * 4);
        float* o = out_zq + (size_t)(base + r) * DDIM + c * 4;
        o[0] = v.x; o[1] = v.y; o[2] = v.z; o[3] = v.w;
    }
}

// ---------------- deterministic loss reduction ----------------
__global__ void finalize_kernel(float* __restrict__ out, int N, float scale) {
    __shared__ float s[512];
    int t = threadIdx.x;
    float v = 0.f;
    for (int i = t; i < N; i += 512)
        v += g_zn2[i] + g_dist[i];
    s[t] = v;
    __syncthreads();
    #pragma unroll
    for (int m = 256; m; m >>= 1) {
        if (t < m) s[t] += s[t + m];
        __syncthreads();
    }
    if (t == 0) out[0] = s[0] * scale;
}

extern "C" void kernel_launch(void* const* d_in, const int* in_sizes, int n_in,
                              void* d_out, int out_size) {
    const float* z = (const float*)d_in[0];
    const float* w = (const float*)d_in[1];
    float* out = (float*)d_out;

    int N = in_sizes[0] / DDIM;   // 65536
    int K = in_sizes[1] / DDIM;   // 1024

    const int dynsmem = A_BYTES + 2 * STG_B;   // 98304 B per CTA, 2 CTAs/SM
    cudaFuncSetAttribute(gemm_kernel, cudaFuncAttributeMaxDynamicSharedMemorySize, dynsmem);

    init_kernel<<<1, 1>>>();                    // 1
    quant_w_kernel<<<K / 8, 256>>>(w);          // 2
    noop_kernel<<<1, 1>>>();                    // 3 (slot filler)
    quant_z_kernel<<<N / 8, 256>>>(z);          // 4  <- ncu capture slot
    gemm_kernel<<<N / BM, 256, dynsmem>>>(N, K);// 5
    refine_kernel<<<RGRID, 256>>>(z, K);        // 6
    output_kernel<<<N / OUTRPB, 256>>>(w, out, N);  // 7
    float scale = 0.25f / ((float)N * (float)DDIM);
    finalize_kernel<<<1, 512>>>(out, N, scale); // 8
}

// round 16
// speedup vs baseline: 1.1739x; 1.1739x over previous
#include <cuda_runtime.h>
#include <cuda_fp16.h>
#include <cstdint>
#include <cstring>

#define DDIM 256
#define NROWS 65536
#define KCODES 1024
#define BM 128
#define BN 128
#define BK 64                 // halves per B stage (128 bytes/row)
#define NCH 8                 // code chunks (1024/128)
#define KS 4                  // k-stages per chunk (256/64)
#define NGS (NCH*KS)          // 32 flat B stages
#define A_BYTES 65536         // resident A: 128 rows x 512 B
#define STG_B 16384           // B stage: 128 rows x 128 B
#define INFV 3.4e38f
#define OUTRPB 16
#define RGRID 256

__device__ __half g_zh[(size_t)NROWS * DDIM];    // 32 MB
__device__ __half g_wh[(size_t)KCODES * DDIM];
__device__ float g_wt[DDIM * KCODES];            // transposed fp32 codebook (refine)
__device__ float g_cnorm[KCODES];
__device__ float g_me[NROWS];                    // per-row certified margin
__device__ float g_zn2[NROWS];                   // exact ||z_row||^2
__device__ float g_dist[NROWS];                  // best (cn - 2*dot) per row
__device__ int   g_init3[3];                     // {flagcount, wmaxbits, dwmaxbits}
__device__ int   g_idx[NROWS];
__device__ int   g_flaglist[NROWS];

#define g_flagcount (g_init3[0])
#define g_wmaxbits  (g_init3[1])
#define g_dwmaxbits (g_init3[2])

__device__ __forceinline__ unsigned h2_bits(__half2 h) {
    unsigned u;
    memcpy(&u, &h, 4);
    return u;
}

// ---------------- prep: quantize w + cnorm + transpose (fused) ----------------
__global__ void quant_w_kernel(const float* __restrict__ w) {
    int warp = threadIdx.x >> 5, lane = threadIdx.x & 31;
    int row = blockIdx.x * 8 + warp;
    const float4* wr = (const float4*)(w + (size_t)row * DDIM);
    float4 v0 = wr[lane * 2], v1 = wr[lane * 2 + 1];
    float v[8] = {v0.x, v0.y, v0.z, v0.w, v1.x, v1.y, v1.z, v1.w};
    __half h[8];
    float sd2 = 0.f, sw2 = 0.f;
    #pragma unroll
    for (int i = 0; i < 8; i++) {
        h[i] = __float2half_rn(v[i]);
        float d = v[i] - __half2float(h[i]);   // exact
        sd2 += d * d;
        sw2 += v[i] * v[i];
        g_wt[(size_t)(lane * 8 + i) * KCODES + row] = v[i];   // transposed copy
    }
    #pragma unroll
    for (int o = 16; o; o >>= 1) {
        sd2 += __shfl_xor_sync(0xffffffffu, sd2, o);
        sw2 += __shfl_xor_sync(0xffffffffu, sw2, o);
    }
    *(uint4*)(g_wh + (size_t)row * DDIM + lane * 8) = *(uint4*)h;
    if (lane == 0) {
        g_cnorm[row] = sw2;
        float wn  = sqrtf(sw2) * 1.0001f + 1e-8f;
        float dwn = sqrtf(sd2) * 1.0001f + 1e-8f;
        atomicMax(&g_wmaxbits, __float_as_int(wn));
        atomicMax(&g_dwmaxbits, __float_as_int(dwn));
    }
}

// quant_z: exact error norms (DRAM-bound kernel; reductions are free)
__global__ void quant_z_kernel(const float* __restrict__ z) {
    int warp = threadIdx.x >> 5, lane = threadIdx.x & 31;
    int row = blockIdx.x * 8 + warp;
    const float4* zr = (const float4*)(z + (size_t)row * DDIM);
    float4 v0 = zr[lane * 2], v1 = zr[lane * 2 + 1];
    float v[8] = {v0.x, v0.y, v0.z, v0.w, v1.x, v1.y, v1.z, v1.w};
    __half2 hp[4];
    hp[0] = __float22half2_rn(make_float2(v0.x, v0.y));
    hp[1] = __float22half2_rn(make_float2(v0.z, v0.w));
    hp[2] = __float22half2_rn(make_float2(v1.x, v1.y));
    hp[3] = __float22half2_rn(make_float2(v1.z, v1.w));
    float sd2 = 0.f, sh2 = 0.f, sz2 = 0.f;
    #pragma unroll
    for (int i = 0; i < 4; i++) {
        float2 hf = __half22float2(hp[i]);
        float a = v[2*i], b = v[2*i+1];
        float da = a - hf.x, db = b - hf.y;      // exact
        sd2 += da*da + db*db;
        sh2 += hf.x*hf.x + hf.y*hf.y;
        sz2 += a*a + b*b;
    }
    #pragma unroll
    for (int o = 16; o; o >>= 1) {
        sd2 += __shfl_xor_sync(0xffffffffu, sd2, o);
        sh2 += __shfl_xor_sync(0xffffffffu, sh2, o);
        sz2 += __shfl_xor_sync(0xffffffffu, sz2, o);
    }
    uint4 pk;
    pk.x = h2_bits(hp[0]); pk.y = h2_bits(hp[1]);
    pk.z = h2_bits(hp[2]); pk.w = h2_bits(hp[3]);
    *(uint4*)(g_zh + (size_t)row * DDIM + lane * 8) = pk;
    if (lane == 0) {
        g_zn2[row] = sz2;
        float dzn = sqrtf(sd2) * 1.0001f + 1e-8f;
        float zhn = sqrtf(sh2) * 1.0001f;
        float wmax  = __int_as_float(g_wmaxbits);
        float dwmax = __int_as_float(g_dwmaxbits);
        g_me[row] = 4.f * (dzn * wmax + zhn * dwmax) + 0.01f;
    }
}

// ---------------- GEMM helpers ----------------
__device__ __forceinline__ void cp16(unsigned saddr, const void* gaddr) {
    asm volatile("cp.async.cg.shared.global [%0], [%1], 16;\n" :: "r"(saddr), "l"(gaddr) : "memory");
}
__device__ __forceinline__ void cp_commit() { asm volatile("cp.async.commit_group;\n" ::: "memory"); }
template<int P> __device__ __forceinline__ void cp_wait() {
    asm volatile("cp.async.wait_group %0;\n" :: "n"(P) : "memory");
}
__device__ __forceinline__ void ldsm4(unsigned a, unsigned &r0, unsigned &r1, unsigned &r2, unsigned &r3) {
    asm volatile("ldmatrix.sync.aligned.m8n8.x4.shared.b16 {%0,%1,%2,%3}, [%4];"
                 : "=r"(r0), "=r"(r1), "=r"(r2), "=r"(r3) : "r"(a));
}
__device__ __forceinline__ void mma16816(float* c, const unsigned* a, const unsigned* b) {
    asm volatile("mma.sync.aligned.m16n8k16.row.col.f32.f16.f16.f32 "
                 "{%0,%1,%2,%3}, {%4,%5,%6,%7}, {%8,%9}, {%0,%1,%2,%3};"
                 : "+f"(c[0]), "+f"(c[1]), "+f"(c[2]), "+f"(c[3])
                 : "r"(a[0]), "r"(a[1]), "r"(a[2]), "r"(a[3]), "r"(b[0]), "r"(b[1]));
}
__device__ __forceinline__ bool lexless(float v, int i, float w, int j) {
    return v < w || (v == w && i < j);
}
__device__ __forceinline__ void top2_merge(float &v1, int &i1, float &v2, int &i2,
                                           float w1, int j1, float w2, int j2) {
    if (lexless(w1, j1, v1, i1)) {
        float nv2; int ni2;
        if (lexless(v1, i1, w2, j2)) { nv2 = v1; ni2 = i1; } else { nv2 = w2; ni2 = j2; }
        v1 = w1; i1 = j1; v2 = nv2; i2 = ni2;
    } else if (lexless(w1, j1, v2, i2)) {
        v2 = w1; i2 = j1;
    }
}

// B-tile swizzle (128B rows): chunk s (16B) of row r -> s ^ (r&7)
__device__ __forceinline__ unsigned sw_off(int row, int bytecol) {
    unsigned off = (unsigned)(row * 128 + bytecol);
    return off ^ ((unsigned)(row & 7) << 4);
}
// A-resident swizzle (512B rows)
__device__ __forceinline__ unsigned sw_offA(int row, int c16) {
    return (unsigned)(row * 512) + ((unsigned)(c16 ^ (row & 7)) << 4);
}

// ---------------- main fp16 GEMM (R12 config: A-resident, B double-buffered) ----------------
__global__ void __launch_bounds__(256, 2)
gemm_kernel(int N, int K)
{
    extern __shared__ __align__(128) char dynsmem[];   // [A 64K | B0 16K | B1 16K]
    __shared__ float  s_cn[KCODES];
    __shared__ float4 s_part[2][BM];

    const int tid  = threadIdx.x;
    const int lane = tid & 31;
    const int warp = tid >> 5;
    const int mw   = warp & 3;
    const int nw   = warp >> 2;
    const int wm0  = mw * 32;
    const int wn0  = nw * 64;
    const int rowBase = blockIdx.x * BM;

    const unsigned sbase = (unsigned)__cvta_generic_to_shared(dynsmem);
    const unsigned bring = sbase + A_BYTES;

    #pragma unroll
    for (int i = tid; i < KCODES; i += 256) s_cn[i] = g_cnorm[i];

    {
        const __half* zp = g_zh + (size_t)(rowBase + (tid >> 1)) * DDIM + (tid & 1) * 128;
        int r = tid >> 1;
        int c0 = (tid & 1) * 16;
        #pragma unroll
        for (int it = 0; it < 16; it++)
            cp16(sbase + sw_offA(r, c0 + it), zp + it * 8);
        cp_commit();
    }

    const __half* wptr = g_wh + (size_t)(tid >> 3) * DDIM + (tid & 7) * 8;
    const unsigned bsw0 = sw_off(tid >> 3, (tid & 7) * 16);

    auto load_B = [&](int gs) {
        unsigned bs_ = bring + (unsigned)(gs & 1) * STG_B;
        const __half* pb = wptr + (gs >> 2) * (BN * DDIM) + (gs & 3) * BK;
        #pragma unroll
        for (int it = 0; it < 4; it++)
            cp16(bs_ + bsw0 + it * 4096, pb + it * 32 * DDIM);
        cp_commit();
    };

    unsigned aAbase[2], a6[2];
    #pragma unroll
    for (int i = 0; i < 2; i++) {
        int arow = wm0 + i * 16 + (lane & 15);
        aAbase[i] = (unsigned)(arow * 512) + ((unsigned)(((lane >> 4) ^ arow) & 1) << 4);
        a6[i] = (unsigned)(arow & 6) << 4;
    }
    unsigned boff[4];
    #pragma unroll
    for (int p = 0; p < 4; p++)
        boff[p] = sw_off(wn0 + p * 16 + (lane & 7) + ((lane >> 4) << 3),
                         (((lane >> 3) & 1) << 3) * 2);

    float rv1[4], rv2[4];
    int   ri1[4], ri2[4];
    #pragma unroll
    for (int s = 0; s < 4; s++) { rv1[s] = INFV; rv2[s] = INFV; ri1[s] = 0x7fffffff; ri2[s] = 0x7fffffff; }

    load_B(0);

    for (int ch = 0; ch < NCH; ch++) {
        float acc[2][8][4];
        #pragma unroll
        for (int i = 0; i < 2; i++)
            #pragma unroll
            for (int j = 0; j < 8; j++)
                #pragma unroll
                for (int c = 0; c < 4; c++) acc[i][j][c] = 0.f;

        #pragma unroll
        for (int ks = 0; ks < KS; ks++) {
            const int gs = ch * KS + ks;
            cp_wait<0>();
            __syncthreads();
            if (gs + 1 < NGS) load_B(gs + 1);

            const unsigned bbase = bring + (unsigned)(gs & 1) * STG_B;
            #pragma unroll
            for (int kk = 0; kk < BK; kk += 16) {
                const unsigned kkb = (unsigned)kk * 2;
                unsigned a[2][4];
                #pragma unroll
                for (int i = 0; i < 2; i++)
                    ldsm4(sbase + aAbase[i] + (unsigned)(ks * 128) + (kkb ^ a6[i]),
                          a[i][0], a[i][1], a[i][2], a[i][3]);
                unsigned b[8][2];
                #pragma unroll
                for (int p = 0; p < 4; p++)
                    ldsm4(bbase + (boff[p] ^ kkb), b[2*p][0], b[2*p][1], b[2*p+1][0], b[2*p+1][1]);
                #pragma unroll
                for (int i = 0; i < 2; i++)
                    #pragma unroll
                    for (int j = 0; j < 8; j++)
                        mma16816(acc[i][j], a[i], b[j]);
            }
        }

        #pragma unroll
        for (int i = 0; i < 2; i++) {
            #pragma unroll
            for (int h = 0; h < 2; h++) {
                const int s = i * 2 + h;
                float v1 = rv1[s], v2 = rv2[s];
                int   i1 = ri1[s], i2 = ri2[s];
                #pragma unroll
                for (int j = 0; j < 8; j++) {
                    #pragma unroll
                    for (int c = 0; c < 2; c++) {
                        int col = wn0 + j * 8 + (lane & 3) * 2 + c;
                        int idx = ch * BN + col;
                        float val = fmaf(-2.f, acc[i][j][h * 2 + c], s_cn[idx]);
                        if (val < v1) { v2 = v1; i2 = i1; v1 = val; i1 = idx; }
                        else if (val < v2) { v2 = val; i2 = idx; }
                    }
                }
                rv1[s] = v1; rv2[s] = v2; ri1[s] = i1; ri2[s] = i2;
            }
        }
    }

    #pragma unroll
    for (int s = 0; s < 4; s++) {
        float v1 = rv1[s], v2 = rv2[s];
        int   i1 = ri1[s], i2 = ri2[s];
        #pragma unroll
        for (int off = 1; off < 4; off <<= 1) {
            float ov1 = __shfl_xor_sync(0xffffffffu, v1, off);
            int   oi1 = __shfl_xor_sync(0xffffffffu, i1, off);
            float ov2 = __shfl_xor_sync(0xffffffffu, v2, off);
            int   oi2 = __shfl_xor_sync(0xffffffffu, i2, off);
            top2_merge(v1, i1, v2, i2, ov1, oi1, ov2, oi2);
        }
        if ((lane & 3) == 0) {
            int i = s >> 1, h = s & 1;
            int r = wm0 + i * 16 + (lane >> 2) + h * 8;
            s_part[nw][r] = make_float4(v1, __int_as_float(i1), v2, __int_as_float(i2));
        }
    }
    __syncthreads();
    if (tid < BM) {
        float4 pa = s_part[0][tid];
        float4 pb = s_part[1][tid];
        float v1 = pa.x; int i1 = __float_as_int(pa.y);
        float v2 = pa.z; int i2 = __float_as_int(pa.w);
        top2_merge(v1, i1, v2, i2, pb.x, __float_as_int(pb.y), pb.z, __float_as_int(pb.w));
        int row = rowBase + tid;
        g_idx[row] = i1;
        g_dist[row] = v1;
        if (v2 - v1 <= g_me[row]) {
            int pos = atomicAdd(&g_flagcount, 1);
            g_flaglist[pos] = row;
        }
    }
}

// ---------------- exact refine of flagged rows (wT-based, FMA-bound) ----------------
__global__ void refine_kernel(const float* __restrict__ z, int K) {
    __shared__ __align__(16) float zs[8][260];
    __shared__ int   rowids[8];
    __shared__ float sbv[8][8];
    __shared__ int   sbi[8][8];

    const int tid  = threadIdx.x;
    const int lane = tid & 31;
    const int warp = tid >> 5;
    const int fcount = g_flagcount;

    for (int base = blockIdx.x * 8; base < fcount; base += gridDim.x * 8) {
        int cnt = min(8, fcount - base);
        if (tid < cnt) rowids[tid] = g_flaglist[base + tid];
        __syncthreads();
        for (int e = tid; e < cnt * 256; e += 256)
            zs[e >> 8][e & 255] = z[(size_t)rowids[e >> 8] * DDIM + (e & 255)];
        __syncthreads();

        float bv[8]; int bi[8];
        #pragma unroll
        for (int r = 0; r < 8; r++) { bv[r] = INFV; bi[r] = 0x7fffffff; }

        #pragma unroll 1
        for (int p = 0; p < 4; p++) {
            int k = p * 256 + tid;
            float acc[8];
            #pragma unroll
            for (int r = 0; r < 8; r++) acc[r] = 0.f;
            #pragma unroll 4
            for (int d4 = 0; d4 < 64; d4++) {
                float w0 = g_wt[(size_t)(d4 * 4 + 0) * KCODES + k];
                float w1 = g_wt[(size_t)(d4 * 4 + 1) * KCODES + k];
                float w2 = g_wt[(size_t)(d4 * 4 + 2) * KCODES + k];
                float w3 = g_wt[(size_t)(d4 * 4 + 3) * KCODES + k];
                #pragma unroll
                for (int r = 0; r < 8; r++) {
                    float4 zv = *(const float4*)&zs[r][d4 * 4];
                    acc[r] = fmaf(zv.x, w0, acc[r]);
                    acc[r] = fmaf(zv.y, w1, acc[r]);
                    acc[r] = fmaf(zv.z, w2, acc[r]);
                    acc[r] = fmaf(zv.w, w3, acc[r]);
                }
            }
            float cn = g_cnorm[k];
            #pragma unroll
            for (int r = 0; r < 8; r++) {
                float val = fmaf(-2.f, acc[r], cn);
                if (lexless(val, k, bv[r], bi[r])) { bv[r] = val; bi[r] = k; }
            }
        }

        #pragma unroll
        for (int r = 0; r < 8; r++) {
            float v = bv[r]; int i = bi[r];
            #pragma unroll
            for (int off = 16; off; off >>= 1) {
                float ov = __shfl_xor_sync(0xffffffffu, v, off);
                int   oi = __shfl_xor_sync(0xffffffffu, i, off);
                if (lexless(ov, oi, v, i)) { v = ov; i = oi; }
            }
            if (lane == 0) { sbv[warp][r] = v; sbi[warp][r] = i; }
        }
        __syncthreads();
        if (tid < cnt) {
            float v = sbv[0][tid]; int i = sbi[0][tid];
            #pragma unroll
            for (int wq = 1; wq < 8; wq++)
                if (lexless(sbv[wq][tid], sbi[wq][tid], v, i)) { v = sbv[wq][tid]; i = sbi[wq][tid]; }
            g_idx[rowids[tid]] = i;
            g_dist[rowids[tid]] = v;
        }
        __syncthreads();
    }
}

// ---------------- output assembly: smem-staged, aligned STG.128 ----------------
__global__ void output_kernel(const float* __restrict__ w, float* __restrict__ out, int N)
{
    __shared__ int s_idx[OUTRPB];
    __shared__ __align__(16) float s_w[OUTRPB][DDIM];
    const int tid = threadIdx.x;
    const int base = blockIdx.x * OUTRPB;

    float* out_zq  = out + 1;
    float* out_idx = out + 1 + (size_t)N * DDIM;

    if (tid < OUTRPB) {
        int ix = g_idx[base + tid];
        s_idx[tid] = ix;
        out_idx[base + tid] = (float)ix;
    }
    __syncthreads();

    // stage 16 codebook rows into smem (aligned float4 loads, coalesced)
    #pragma unroll
    for (int i = tid; i < OUTRPB * 64; i += 256) {
        int r = i >> 6, c = i & 63;
        *(float4*)&s_w[r][c * 4] = *(const float4*)(w + (size_t)s_idx[r] * DDIM + c * 4);
    }
    __syncthreads();

    // head (e=0,1,2) + tail (e=255) scalars: 64 threads
    if (tid < OUTRPB * 4) {
        int r = tid >> 2, q = tid & 3;
        int e = (q < 3) ? q : 255;
        out_zq[(size_t)(base + r) * DDIM + e] = s_w[r][e];
    }
    // aligned vector body: e = 3 + 4*c, c in [0,63)
    #pragma unroll
    for (int i = tid; i < OUTRPB * 64; i += 256) {
        int r = i >> 6, c = i & 63;
        if (c < 63) {
            int e = 3 + c * 4;
            float4 v = make_float4(s_w[r][e], s_w[r][e+1], s_w[r][e+2], s_w[r][e+3]);
            *(float4*)(out_zq + (size_t)(base + r) * DDIM + e) = v;
        }
    }
}

// ---------------- deterministic loss reduction ----------------
__global__ void finalize_kernel(float* __restrict__ out, int N, float scale) {
    __shared__ float s[512];
    int t = threadIdx.x;
    float v = 0.f;
    for (int i = t; i < N; i += 512)
        v += g_zn2[i] + g_dist[i];
    s[t] = v;
    __syncthreads();
    #pragma unroll
    for (int m = 256; m; m >>= 1) {
        if (t < m) s[t] += s[t + m];
        __syncthreads();
    }
    if (t == 0) out[0] = s[0] * scale;
}

extern "C" void kernel_launch(void* const* d_in, const int* in_sizes, int n_in,
                              void* d_out, int out_size) {
    const float* z = (const float*)d_in[0];
    const float* w = (const float*)d_in[1];
    float* out = (float*)d_out;

    int N = in_sizes[0] / DDIM;   // 65536
    int K = in_sizes[1] / DDIM;   // 1024

    const int dynsmem = A_BYTES + 2 * STG_B;   // 98304 B per CTA, 2 CTAs/SM
    cudaFuncSetAttribute(gemm_kernel, cudaFuncAttributeMaxDynamicSharedMemorySize, dynsmem);

    void* initPtr = nullptr;
    cudaGetSymbolAddress(&initPtr, g_init3);
    cudaMemsetAsync(initPtr, 0, 3 * sizeof(int));   // graph-capturable

    quant_w_kernel<<<K / 8, 256>>>(w);          // launch 1
    quant_z_kernel<<<N / 8, 256>>>(z);          // launch 2
    gemm_kernel<<<N / BM, 256, dynsmem>>>(N, K);// launch 3
    refine_kernel<<<RGRID, 256>>>(z, K);        // launch 4 <- ncu capture slot
    output_kernel<<<N / OUTRPB, 256>>>(w, out, N);  // 5
    float scale = 0.25f / ((float)N * (float)DDIM);
    finalize_kernel<<<1, 512>>>(out, N, scale); // 6
}

// round 17
// speedup vs baseline: 1.6268x; 1.3858x over previous
#include <cuda_runtime.h>
#include <cuda_fp16.h>
#include <cstdint>
#include <cstring>

#define DDIM 256
#define NROWS 65536
#define KCODES 1024
#define BM 128
#define BN 128
#define BK 64                 // halves per B stage (128 bytes/row)
#define NCH 8                 // code chunks (1024/128)
#define KS 4                  // k-stages per chunk (256/64)
#define NGS (NCH*KS)          // 32 flat B stages
#define A_BYTES 65536         // resident A: 128 rows x 512 B
#define STG_B 16384           // B stage: 128 rows x 128 B
#define INFV 3.4e38f
#define OUTRPB 16
#define RGRID 1024
#define RB 4                  // rows per refine unit

__device__ __half g_zh[(size_t)NROWS * DDIM];    // 32 MB
__device__ __half g_wh[(size_t)KCODES * DDIM];
__device__ float4 g_wt4[64 * KCODES];            // w regrouped: [d4][k] -> w[k][4d4..4d4+3]
__device__ float g_cnorm[KCODES];
__device__ float g_me[NROWS];                    // per-row certified margin
__device__ float g_zn2[NROWS];                   // exact ||z_row||^2
__device__ float g_dist[NROWS];                  // best (cn - 2*dot) per row
__device__ unsigned long long g_packed[NROWS];   // refine accumulator (val,idx)
__device__ int   g_init3[3];                     // {flagcount, wmaxbits, dwmaxbits}
__device__ int   g_idx[NROWS];
__device__ int   g_flaglist[NROWS];

#define g_flagcount (g_init3[0])
#define g_wmaxbits  (g_init3[1])
#define g_dwmaxbits (g_init3[2])

__device__ __forceinline__ unsigned h2_bits(__half2 h) {
    unsigned u;
    memcpy(&u, &h, 4);
    return u;
}
// monotonic float->uint map (preserves <, exact)
__device__ __forceinline__ unsigned fkey(float v) {
    unsigned b = __float_as_uint(v);
    return (b & 0x80000000u) ? ~b : (b | 0x80000000u);
}
__device__ __forceinline__ float fkey_inv(unsigned u) {
    unsigned b = (u & 0x80000000u) ? (u & 0x7fffffffu) : ~u;
    return __uint_as_float(b);
}

// ---------------- prep: quantize w + cnorm + d4-grouped transpose (fused) ----------------
__global__ void quant_w_kernel(const float* __restrict__ w) {
    int warp = threadIdx.x >> 5, lane = threadIdx.x & 31;
    int row = blockIdx.x * 8 + warp;
    const float4* wr = (const float4*)(w + (size_t)row * DDIM);
    float4 v0 = wr[lane * 2], v1 = wr[lane * 2 + 1];
    float v[8] = {v0.x, v0.y, v0.z, v0.w, v1.x, v1.y, v1.z, v1.w};
    __half h[8];
    float sd2 = 0.f, sw2 = 0.f;
    #pragma unroll
    for (int i = 0; i < 8; i++) {
        h[i] = __float2half_rn(v[i]);
        float d = v[i] - __half2float(h[i]);   // exact
        sd2 += d * d;
        sw2 += v[i] * v[i];
    }
    g_wt4[(lane * 2 + 0) * KCODES + row] = v0;
    g_wt4[(lane * 2 + 1) * KCODES + row] = v1;
    #pragma unroll
    for (int o = 16; o; o >>= 1) {
        sd2 += __shfl_xor_sync(0xffffffffu, sd2, o);
        sw2 += __shfl_xor_sync(0xffffffffu, sw2, o);
    }
    *(uint4*)(g_wh + (size_t)row * DDIM + lane * 8) = *(uint4*)h;
    if (lane == 0) {
        g_cnorm[row] = sw2;
        float wn  = sqrtf(sw2) * 1.0001f + 1e-8f;
        float dwn = sqrtf(sd2) * 1.0001f + 1e-8f;
        atomicMax(&g_wmaxbits, __float_as_int(wn));
        atomicMax(&g_dwmaxbits, __float_as_int(dwn));
    }
}

// quant_z: exact error norms (DRAM-bound kernel; reductions are free)
__global__ void quant_z_kernel(const float* __restrict__ z) {
    int warp = threadIdx.x >> 5, lane = threadIdx.x & 31;
    int row = blockIdx.x * 8 + warp;
    const float4* zr = (const float4*)(z + (size_t)row * DDIM);
    float4 v0 = zr[lane * 2], v1 = zr[lane * 2 + 1];
    float v[8] = {v0.x, v0.y, v0.z, v0.w, v1.x, v1.y, v1.z, v1.w};
    __half2 hp[4];
    hp[0] = __float22half2_rn(make_float2(v0.x, v0.y));
    hp[1] = __float22half2_rn(make_float2(v0.z, v0.w));
    hp[2] = __float22half2_rn(make_float2(v1.x, v1.y));
    hp[3] = __float22half2_rn(make_float2(v1.z, v1.w));
    float sd2 = 0.f, sh2 = 0.f, sz2 = 0.f;
    #pragma unroll
    for (int i = 0; i < 4; i++) {
        float2 hf = __half22float2(hp[i]);
        float a = v[2*i], b = v[2*i+1];
        float da = a - hf.x, db = b - hf.y;      // exact
        sd2 += da*da + db*db;
        sh2 += hf.x*hf.x + hf.y*hf.y;
        sz2 += a*a + b*b;
    }
    #pragma unroll
    for (int o = 16; o; o >>= 1) {
        sd2 += __shfl_xor_sync(0xffffffffu, sd2, o);
        sh2 += __shfl_xor_sync(0xffffffffu, sh2, o);
        sz2 += __shfl_xor_sync(0xffffffffu, sz2, o);
    }
    uint4 pk;
    pk.x = h2_bits(hp[0]); pk.y = h2_bits(hp[1]);
    pk.z = h2_bits(hp[2]); pk.w = h2_bits(hp[3]);
    *(uint4*)(g_zh + (size_t)row * DDIM + lane * 8) = pk;
    if (lane == 0) {
        g_zn2[row] = sz2;
        float dzn = sqrtf(sd2) * 1.0001f + 1e-8f;
        float zhn = sqrtf(sh2) * 1.0001f;
        float wmax  = __int_as_float(g_wmaxbits);
        float dwmax = __int_as_float(g_dwmaxbits);
        g_me[row] = 4.f * (dzn * wmax + zhn * dwmax) + 0.01f;
    }
}

// ---------------- GEMM helpers ----------------
__device__ __forceinline__ void cp16(unsigned saddr, const void* gaddr) {
    asm volatile("cp.async.cg.shared.global [%0], [%1], 16;\n" :: "r"(saddr), "l"(gaddr) : "memory");
}
__device__ __forceinline__ void cp_commit() { asm volatile("cp.async.commit_group;\n" ::: "memory"); }
template<int P> __device__ __forceinline__ void cp_wait() {
    asm volatile("cp.async.wait_group %0;\n" :: "n"(P) : "memory");
}
__device__ __forceinline__ void ldsm4(unsigned a, unsigned &r0, unsigned &r1, unsigned &r2, unsigned &r3) {
    asm volatile("ldmatrix.sync.aligned.m8n8.x4.shared.b16 {%0,%1,%2,%3}, [%4];"
                 : "=r"(r0), "=r"(r1), "=r"(r2), "=r"(r3) : "r"(a));
}
__device__ __forceinline__ void mma16816(float* c, const unsigned* a, const unsigned* b) {
    asm volatile("mma.sync.aligned.m16n8k16.row.col.f32.f16.f16.f32 "
                 "{%0,%1,%2,%3}, {%4,%5,%6,%7}, {%8,%9}, {%0,%1,%2,%3};"
                 : "+f"(c[0]), "+f"(c[1]), "+f"(c[2]), "+f"(c[3])
                 : "r"(a[0]), "r"(a[1]), "r"(a[2]), "r"(a[3]), "r"(b[0]), "r"(b[1]));
}
__device__ __forceinline__ bool lexless(float v, int i, float w, int j) {
    return v < w || (v == w && i < j);
}
__device__ __forceinline__ void top2_merge(float &v1, int &i1, float &v2, int &i2,
                                           float w1, int j1, float w2, int j2) {
    if (lexless(w1, j1, v1, i1)) {
        float nv2; int ni2;
        if (lexless(v1, i1, w2, j2)) { nv2 = v1; ni2 = i1; } else { nv2 = w2; ni2 = j2; }
        v1 = w1; i1 = j1; v2 = nv2; i2 = ni2;
    } else if (lexless(w1, j1, v2, i2)) {
        v2 = w1; i2 = j1;
    }
}

__device__ __forceinline__ unsigned sw_off(int row, int bytecol) {
    unsigned off = (unsigned)(row * 128 + bytecol);
    return off ^ ((unsigned)(row & 7) << 4);
}
__device__ __forceinline__ unsigned sw_offA(int row, int c16) {
    return (unsigned)(row * 512) + ((unsigned)(c16 ^ (row & 7)) << 4);
}

// ---------------- main fp16 GEMM (A-resident, B double-buffered) ----------------
__global__ void __launch_bounds__(256, 2)
gemm_kernel(int N, int K)
{
    extern __shared__ __align__(128) char dynsmem[];   // [A 64K | B0 16K | B1 16K]
    __shared__ float  s_cn[KCODES];
    __shared__ float4 s_part[2][BM];

    const int tid  = threadIdx.x;
    const int lane = tid & 31;
    const int warp = tid >> 5;
    const int mw   = warp & 3;
    const int nw   = warp >> 2;
    const int wm0  = mw * 32;
    const int wn0  = nw * 64;
    const int rowBase = blockIdx.x * BM;

    const unsigned sbase = (unsigned)__cvta_generic_to_shared(dynsmem);
    const unsigned bring = sbase + A_BYTES;

    #pragma unroll
    for (int i = tid; i < KCODES; i += 256) s_cn[i] = g_cnorm[i];

    {
        const __half* zp = g_zh + (size_t)(rowBase + (tid >> 1)) * DDIM + (tid & 1) * 128;
        int r = tid >> 1;
        int c0 = (tid & 1) * 16;
        #pragma unroll
        for (int it = 0; it < 16; it++)
            cp16(sbase + sw_offA(r, c0 + it), zp + it * 8);
        cp_commit();
    }

    const __half* wptr = g_wh + (size_t)(tid >> 3) * DDIM + (tid & 7) * 8;
    const unsigned bsw0 = sw_off(tid >> 3, (tid & 7) * 16);

    auto load_B = [&](int gs) {
        unsigned bs_ = bring + (unsigned)(gs & 1) * STG_B;
        const __half* pb = wptr + (gs >> 2) * (BN * DDIM) + (gs & 3) * BK;
        #pragma unroll
        for (int it = 0; it < 4; it++)
            cp16(bs_ + bsw0 + it * 4096, pb + it * 32 * DDIM);
        cp_commit();
    };

    unsigned aAbase[2], a6[2];
    #pragma unroll
    for (int i = 0; i < 2; i++) {
        int arow = wm0 + i * 16 + (lane & 15);
        aAbase[i] = (unsigned)(arow * 512) + ((unsigned)(((lane >> 4) ^ arow) & 1) << 4);
        a6[i] = (unsigned)(arow & 6) << 4;
    }
    unsigned boff[4];
    #pragma unroll
    for (int p = 0; p < 4; p++)
        boff[p] = sw_off(wn0 + p * 16 + (lane & 7) + ((lane >> 4) << 3),
                         (((lane >> 3) & 1) << 3) * 2);

    float rv1[4], rv2[4];
    int   ri1[4], ri2[4];
    #pragma unroll
    for (int s = 0; s < 4; s++) { rv1[s] = INFV; rv2[s] = INFV; ri1[s] = 0x7fffffff; ri2[s] = 0x7fffffff; }

    load_B(0);

    for (int ch = 0; ch < NCH; ch++) {
        float acc[2][8][4];
        #pragma unroll
        for (int i = 0; i < 2; i++)
            #pragma unroll
            for (int j = 0; j < 8; j++)
                #pragma unroll
                for (int c = 0; c < 4; c++) acc[i][j][c] = 0.f;

        #pragma unroll
        for (int ks = 0; ks < KS; ks++) {
            const int gs = ch * KS + ks;
            cp_wait<0>();
            __syncthreads();
            if (gs + 1 < NGS) load_B(gs + 1);

            const unsigned bbase = bring + (unsigned)(gs & 1) * STG_B;
            #pragma unroll
            for (int kk = 0; kk < BK; kk += 16) {
                const unsigned kkb = (unsigned)kk * 2;
                unsigned a[2][4];
                #pragma unroll
                for (int i = 0; i < 2; i++)
                    ldsm4(sbase + aAbase[i] + (unsigned)(ks * 128) + (kkb ^ a6[i]),
                          a[i][0], a[i][1], a[i][2], a[i][3]);
                unsigned b[8][2];
                #pragma unroll
                for (int p = 0; p < 4; p++)
                    ldsm4(bbase + (boff[p] ^ kkb), b[2*p][0], b[2*p][1], b[2*p+1][0], b[2*p+1][1]);
                #pragma unroll
                for (int i = 0; i < 2; i++)
                    #pragma unroll
                    for (int j = 0; j < 8; j++)
                        mma16816(acc[i][j], a[i], b[j]);
            }
        }

        #pragma unroll
        for (int i = 0; i < 2; i++) {
            #pragma unroll
            for (int h = 0; h < 2; h++) {
                const int s = i * 2 + h;
                float v1 = rv1[s], v2 = rv2[s];
                int   i1 = ri1[s], i2 = ri2[s];
                #pragma unroll
                for (int j = 0; j < 8; j++) {
                    #pragma unroll
                    for (int c = 0; c < 2; c++) {
                        int col = wn0 + j * 8 + (lane & 3) * 2 + c;
                        int idx = ch * BN + col;
                        float val = fmaf(-2.f, acc[i][j][h * 2 + c], s_cn[idx]);
                        if (val < v1) { v2 = v1; i2 = i1; v1 = val; i1 = idx; }
                        else if (val < v2) { v2 = val; i2 = idx; }
                    }
                }
                rv1[s] = v1; rv2[s] = v2; ri1[s] = i1; ri2[s] = i2;
            }
        }
    }

    #pragma unroll
    for (int s = 0; s < 4; s++) {
        float v1 = rv1[s], v2 = rv2[s];
        int   i1 = ri1[s], i2 = ri2[s];
        #pragma unroll
        for (int off = 1; off < 4; off <<= 1) {
            float ov1 = __shfl_xor_sync(0xffffffffu, v1, off);
            int   oi1 = __shfl_xor_sync(0xffffffffu, i1, off);
            float ov2 = __shfl_xor_sync(0xffffffffu, v2, off);
            int   oi2 = __shfl_xor_sync(0xffffffffu, i2, off);
            top2_merge(v1, i1, v2, i2, ov1, oi1, ov2, oi2);
        }
        if ((lane & 3) == 0) {
            int i = s >> 1, h = s & 1;
            int r = wm0 + i * 16 + (lane >> 2) + h * 8;
            s_part[nw][r] = make_float4(v1, __int_as_float(i1), v2, __int_as_float(i2));
        }
    }
    __syncthreads();
    if (tid < BM) {
        float4 pa = s_part[0][tid];
        float4 pb = s_part[1][tid];
        float v1 = pa.x; int i1 = __float_as_int(pa.y);
        float v2 = pa.z; int i2 = __float_as_int(pa.w);
        top2_merge(v1, i1, v2, i2, pb.x, __float_as_int(pb.y), pb.z, __float_as_int(pb.w));
        int row = rowBase + tid;
        g_idx[row] = i1;
        g_dist[row] = v1;
        if (v2 - v1 <= g_me[row]) {
            g_packed[row] = 0xFFFFFFFFFFFFFFFFull;
            int pos = atomicAdd(&g_flagcount, 1);
            g_flaglist[pos] = row;
        }
    }
}

// ---------------- refine v2: (4-row group x code-half) units, atomicMin combine ----------------
__global__ void refine_kernel(const float* __restrict__ z, int K) {
    __shared__ __align__(16) float zs[RB][DDIM];
    __shared__ int rowids[RB];

    const int tid = threadIdx.x;
    const int fcount = g_flagcount;
    const int ngroups = (fcount + RB - 1) / RB;
    const int nunits  = ngroups * 2;

    for (int u = blockIdx.x; u < nunits; u += gridDim.x) {
        const int g = u >> 1;
        const int half = u & 1;
        const int base = g * RB;
        const int cnt = min(RB, fcount - base);

        if (tid < cnt) rowids[tid] = g_flaglist[base + tid];
        __syncthreads();
        for (int e = tid; e < cnt * 64; e += 256) {
            int r = e >> 6, c = e & 63;
            *(float4*)&zs[r][c * 4] = *(const float4*)(z + (size_t)rowids[r] * DDIM + c * 4);
        }
        __syncthreads();

        const int k0 = half * 512 + tid;     // two codes: k0, k0+256
        float acc[RB][2];
        #pragma unroll
        for (int r = 0; r < RB; r++) { acc[r][0] = 0.f; acc[r][1] = 0.f; }

        #pragma unroll 4
        for (int d4 = 0; d4 < 64; d4++) {
            float4 w0 = g_wt4[d4 * KCODES + k0];
            float4 w1 = g_wt4[d4 * KCODES + k0 + 256];
            #pragma unroll
            for (int r = 0; r < RB; r++) {
                float4 zv = *(const float4*)&zs[r][d4 * 4];
                acc[r][0] = fmaf(zv.x, w0.x, acc[r][0]);
                acc[r][0] = fmaf(zv.y, w0.y, acc[r][0]);
                acc[r][0] = fmaf(zv.z, w0.z, acc[r][0]);
                acc[r][0] = fmaf(zv.w, w0.w, acc[r][0]);
                acc[r][1] = fmaf(zv.x, w1.x, acc[r][1]);
                acc[r][1] = fmaf(zv.y, w1.y, acc[r][1]);
                acc[r][1] = fmaf(zv.z, w1.z, acc[r][1]);
                acc[r][1] = fmaf(zv.w, w1.w, acc[r][1]);
            }
        }

        float cn0 = g_cnorm[k0], cn1 = g_cnorm[k0 + 256];
        #pragma unroll
        for (int r = 0; r < RB; r++) {
            if (r >= cnt) break;
            float v0 = fmaf(-2.f, acc[r][0], cn0);
            float v1 = fmaf(-2.f, acc[r][1], cn1);
            float bv; int bi;
            if (lexless(v0, k0, v1, k0 + 256)) { bv = v0; bi = k0; }
            else { bv = v1; bi = k0 + 256; }
            unsigned long long key = ((unsigned long long)fkey(bv) << 32) | (unsigned)bi;
            // warp-level min of keys first (cuts atomics 32x)
            #pragma unroll
            for (int off = 16; off; off >>= 1) {
                unsigned long long ok = __shfl_xor_sync(0xffffffffu, key, off);
                key = min(key, ok);
            }
            if ((tid & 31) == 0) atomicMin(&g_packed[rowids[r]], key);
        }
        __syncthreads();
    }
}

// ---------------- unflag: unpack refined results ----------------
__global__ void unflag_kernel() {
    const int fcount = g_flagcount;
    for (int i = blockIdx.x * blockDim.x + threadIdx.x; i < fcount; i += gridDim.x * blockDim.x) {
        int row = g_flaglist[i];
        unsigned long long key = g_packed[row];
        g_idx[row]  = (int)(key & 0xFFFFFFFFull);
        g_dist[row] = fkey_inv((unsigned)(key >> 32));
    }
}

// ---------------- output assembly: smem-staged, aligned STG.128 ----------------
__global__ void output_kernel(const float* __restrict__ w, float* __restrict__ out, int N)
{
    __shared__ int s_idx[OUTRPB];
    __shared__ __align__(16) float s_w[OUTRPB][DDIM];
    const int tid = threadIdx.x;
    const int base = blockIdx.x * OUTRPB;

    float* out_zq  = out + 1;
    float* out_idx = out + 1 + (size_t)N * DDIM;

    if (tid < OUTRPB) {
        int ix = g_idx[base + tid];
        s_idx[tid] = ix;
        out_idx[base + tid] = (float)ix;
    }
    __syncthreads();

    #pragma unroll
    for (int i = tid; i < OUTRPB * 64; i += 256) {
        int r = i >> 6, c = i & 63;
        *(float4*)&s_w[r][c * 4] = *(const float4*)(w + (size_t)s_idx[r] * DDIM + c * 4);
    }
    __syncthreads();

    if (tid < OUTRPB * 4) {
        int r = tid >> 2, q = tid & 3;
        int e = (q < 3) ? q : 255;
        out_zq[(size_t)(base + r) * DDIM + e] = s_w[r][e];
    }
    #pragma unroll
    for (int i = tid; i < OUTRPB * 64; i += 256) {
        int r = i >> 6, c = i & 63;
        if (c < 63) {
            int e = 3 + c * 4;
            float4 v = make_float4(s_w[r][e], s_w[r][e+1], s_w[r][e+2], s_w[r][e+3]);
            *(float4*)(out_zq + (size_t)(base + r) * DDIM + e) = v;
        }
    }
}

// ---------------- deterministic loss reduction ----------------
__global__ void finalize_kernel(float* __restrict__ out, int N, float scale) {
    __shared__ float s[512];
    int t = threadIdx.x;
    float v = 0.f;
    for (int i = t; i < N; i += 512)
        v += g_zn2[i] + g_dist[i];
    s[t] = v;
    __syncthreads();
    #pragma unroll
    for (int m = 256; m; m >>= 1) {
        if (t < m) s[t] += s[t + m];
        __syncthreads();
    }
    if (t == 0) out[0] = s[0] * scale;
}

extern "C" void kernel_launch(void* const* d_in, const int* in_sizes, int n_in,
                              void* d_out, int out_size) {
    const float* z = (const float*)d_in[0];
    const float* w = (const float*)d_in[1];
    float* out = (float*)d_out;

    int N = in_sizes[0] / DDIM;   // 65536
    int K = in_sizes[1] / DDIM;   // 1024

    const int dynsmem = A_BYTES + 2 * STG_B;   // 98304 B per CTA, 2 CTAs/SM
    cudaFuncSetAttribute(gemm_kernel, cudaFuncAttributeMaxDynamicSharedMemorySize, dynsmem);

    void* initPtr = nullptr;
    cudaGetSymbolAddress(&initPtr, g_init3);
    cudaMemsetAsync(initPtr, 0, 3 * sizeof(int));   // graph-capturable

    quant_w_kernel<<<K / 8, 256>>>(w);          // launch 1
    quant_z_kernel<<<N / 8, 256>>>(z);          // launch 2
    gemm_kernel<<<N / BM, 256, dynsmem>>>(N, K);// launch 3
    refine_kernel<<<RGRID, 256>>>(z, K);        // launch 4 <- ncu capture slot
    unflag_kernel<<<16, 256>>>();               // 5
    output_kernel<<<N / OUTRPB, 256>>>(w, out, N);  // 6
    float scale = 0.25f / ((float)N * (float)DDIM);
    finalize_kernel<<<1, 512>>>(out, N, scale); // 7
}